// round 7
// baseline (speedup 1.0000x reference)
#include <cuda_runtime.h>
#include <math.h>

// Problem constants (fixed shapes per reference setup_inputs)
#define NB    2
#define NDIM  128          // D = H = W = 128
#define NC    4            // image channels
#define IMG_ELEMS (NB * NDIM * NDIM * NDIM * NC)   // 16777216

// Double-precision combined (Gauss o cubic-resize) 128x4 per-axis weights.
// G and R are quantized to f32 first (matching jax's f64->f32 weight casts),
// then composed in f64.
__device__ double Mgd[NDIM][4];
// T2d[b][d][h][k][c] = sum_{i,j} M[d][i] M[h][j] coarse[b][i][j][k][c]  (f64)
__device__ double T2d[NB][NDIM][NDIM][4][3];

// ---------------------------------------------------------------------------
// Kernel 1: build M = G @ R (one block, 128 threads).
// R: jax.image.resize cubic (Keys a=-0.5), weights computed in f64,
//    renormalized by (signed) column sum, then cast to f32 (as jax does).
// G: sigma=2.5, taps at a=-7..8 (K=16), normalized in f64, cast to f32.
// M composed in f64 from the f32-quantized factors; zero-padded SAME conv.
// ---------------------------------------------------------------------------
__global__ void build_M_kernel() {
    __shared__ float Rs[NDIM][4];   // f32-quantized resize weights
    int d = threadIdx.x;

    // cubic resize row: sample position for output d, input size 4, scale 32
    double s = (d + 0.5) / 32.0 - 0.5;
    double w[4];
    double sum = 0.0;
    #pragma unroll
    for (int j = 0; j < 4; j++) {
        double x = fabs(s - (double)j);
        double v;
        if (x < 1.0)       v = ((1.5 * x - 2.5) * x) * x + 1.0;
        else if (x < 2.0)  v = ((-0.5 * x + 2.5) * x - 4.0) * x + 2.0;
        else               v = 0.0;
        w[j] = v;
        sum += v;
    }
    #pragma unroll
    for (int j = 0; j < 4; j++) Rs[d][j] = (float)(w[j] / sum);
    __syncthreads();

    // Gaussian taps: ax = -7..8, sigma = 2.5, normalized in f64, cast to f32
    double Graw[16];
    double gs = 0.0;
    #pragma unroll
    for (int t = 0; t < 16; t++) {
        double a = (double)(t - 7);
        Graw[t] = exp(-a * a / (2.0 * 2.5 * 2.5));
        gs += Graw[t];
    }
    float Gf[16];
    #pragma unroll
    for (int t = 0; t < 16; t++) Gf[t] = (float)(Graw[t] / gs);

    // M[d][j] = sum_t G[t] * R[d + t - 7][j], zero-padded outside [0,127]
    #pragma unroll
    for (int j = 0; j < 4; j++) {
        double acc = 0.0;
        #pragma unroll
        for (int t = 0; t < 16; t++) {
            int src = d + t - 7;
            if (src >= 0 && src < NDIM)
                acc += (double)Gf[t] * (double)Rs[src][j];
        }
        Mgd[d][j] = acc;
    }
}

// ---------------------------------------------------------------------------
// Kernel 2: T2d[b][d][h][k][c] — contract coarse flow over D and H axes in
// f64. grid (d, b), block = 128 threads over h. Trivial cost.
// ---------------------------------------------------------------------------
__global__ void build_T2_kernel(const float* __restrict__ coarse) {
    int d = blockIdx.x;
    int b = blockIdx.y;
    int h = threadIdx.x;

    __shared__ double Cs[4 * 4 * 4 * 3];   // 192 values for this batch
    for (int i = h; i < 192; i += blockDim.x) Cs[i] = (double)coarse[b * 192 + i];
    __syncthreads();

    double Md[4], Mh[4];
    #pragma unroll
    for (int i = 0; i < 4; i++) Md[i] = Mgd[d][i];
    #pragma unroll
    for (int j = 0; j < 4; j++) Mh[j] = Mgd[h][j];

    double acc[4][3];
    #pragma unroll
    for (int k = 0; k < 4; k++)
        #pragma unroll
        for (int c = 0; c < 3; c++) acc[k][c] = 0.0;

    #pragma unroll
    for (int i = 0; i < 4; i++) {
        #pragma unroll
        for (int j = 0; j < 4; j++) {
            double wij = Md[i] * Mh[j];
            const double* cij = &Cs[(i * 4 + j) * 4 * 3];
            #pragma unroll
            for (int k = 0; k < 4; k++)
                #pragma unroll
                for (int c = 0; c < 3; c++)
                    acc[k][c] = fma(wij, cij[k * 3 + c], acc[k][c]);
        }
    }
    #pragma unroll
    for (int k = 0; k < 4; k++)
        #pragma unroll
        for (int c = 0; c < 3; c++)
            T2d[b][d][h][k][c] = acc[k][c];
}

// ---------------------------------------------------------------------------
// Kernel 3: main warp. One thread per output voxel (b,d,h,w).
// Flow contraction in f64 (12 DFMA), rounded once to f32, then the exact
// reference f32 roundings: flow*35 (rn mul), grid+flow (rn add).
// Trilinear image sample (8 float4 gathers), nearest label.
// ---------------------------------------------------------------------------
__global__ __launch_bounds__(128) void warp_kernel(
    const float4* __restrict__ img,   // [B,D,H,W] of float4 (C=4)
    const int*    __restrict__ lab,   // [B,D,H,W]
    float*        __restrict__ out)   // image (float4) then label floats
{
    const int w = threadIdx.x;
    const int h = blockIdx.x;
    const int d = blockIdx.y;
    const int b = blockIdx.z;

    __shared__ double t2[12];
    if (w < 12) t2[w] = (&T2d[b][d][h][0][0])[w];
    __syncthreads();

    const double m0 = Mgd[w][0], m1 = Mgd[w][1], m2 = Mgd[w][2], m3 = Mgd[w][3];

    // flow components (c: 0=d, 1=h, 2=w), k-contraction over M[w], f64
    const double fdd = m0 * t2[0] + m1 * t2[3] + m2 * t2[6] + m3 * t2[9];
    const double fhd = m0 * t2[1] + m1 * t2[4] + m2 * t2[7] + m3 * t2[10];
    const double fwd = m0 * t2[2] + m1 * t2[5] + m2 * t2[8] + m3 * t2[11];

    // Replicate reference f32 roundings: flow(f32) -> *35 (f32) -> +grid (f32)
    const float wd = __fadd_rn((float)d, __fmul_rn(35.0f, (float)fdd));
    const float wh = __fadd_rn((float)h, __fmul_rn(35.0f, (float)fhd));
    const float ww = __fadd_rn((float)w, __fmul_rn(35.0f, (float)fwd));

    const float fdf = floorf(wd), fhf = floorf(wh), fwf = floorf(ww);
    const float td = wd - fdf, th = wh - fhf, tw = ww - fwf;

    const int d0 = min(max((int)fdf, 0), NDIM - 1);
    const int h0 = min(max((int)fhf, 0), NDIM - 1);
    const int w0 = min(max((int)fwf, 0), NDIM - 1);
    const int d1 = min(max((int)fdf + 1, 0), NDIM - 1);
    const int h1 = min(max((int)fhf + 1, 0), NDIM - 1);
    const int w1 = min(max((int)fwf + 1, 0), NDIM - 1);

    const int bb = b * NDIM;
    #define VIDX(di, hi, wi) ((((bb + (di)) * NDIM + (hi)) * NDIM) + (wi))

    const float4 v000 = __ldg(&img[VIDX(d0, h0, w0)]);
    const float4 v001 = __ldg(&img[VIDX(d0, h0, w1)]);
    const float4 v010 = __ldg(&img[VIDX(d0, h1, w0)]);
    const float4 v011 = __ldg(&img[VIDX(d0, h1, w1)]);
    const float4 v100 = __ldg(&img[VIDX(d1, h0, w0)]);
    const float4 v101 = __ldg(&img[VIDX(d1, h0, w1)]);
    const float4 v110 = __ldg(&img[VIDX(d1, h1, w0)]);
    const float4 v111 = __ldg(&img[VIDX(d1, h1, w1)]);

    const float omw = 1.0f - tw, omh = 1.0f - th, omd = 1.0f - td;

    float4 c00, c01, c10, c11, c0, c1, res;
    c00.x = v000.x * omw + v001.x * tw;  c00.y = v000.y * omw + v001.y * tw;
    c00.z = v000.z * omw + v001.z * tw;  c00.w = v000.w * omw + v001.w * tw;
    c01.x = v010.x * omw + v011.x * tw;  c01.y = v010.y * omw + v011.y * tw;
    c01.z = v010.z * omw + v011.z * tw;  c01.w = v010.w * omw + v011.w * tw;
    c10.x = v100.x * omw + v101.x * tw;  c10.y = v100.y * omw + v101.y * tw;
    c10.z = v100.z * omw + v101.z * tw;  c10.w = v100.w * omw + v101.w * tw;
    c11.x = v110.x * omw + v111.x * tw;  c11.y = v110.y * omw + v111.y * tw;
    c11.z = v110.z * omw + v111.z * tw;  c11.w = v110.w * omw + v111.w * tw;

    c0.x = c00.x * omh + c01.x * th;  c0.y = c00.y * omh + c01.y * th;
    c0.z = c00.z * omh + c01.z * th;  c0.w = c00.w * omh + c01.w * th;
    c1.x = c10.x * omh + c11.x * th;  c1.y = c10.y * omh + c11.y * th;
    c1.z = c10.z * omh + c11.z * th;  c1.w = c10.w * omh + c11.w * th;

    res.x = c0.x * omd + c1.x * td;  res.y = c0.y * omd + c1.y * td;
    res.z = c0.z * omd + c1.z * td;  res.w = c0.w * omd + c1.w * td;

    const int lin = VIDX(d, h, w);
    reinterpret_cast<float4*>(out)[lin] = res;

    // nearest-neighbor label: jnp.round == round-half-to-even == rintf
    const int nd = min(max((int)rintf(wd), 0), NDIM - 1);
    const int nh = min(max((int)rintf(wh), 0), NDIM - 1);
    const int nw = min(max((int)rintf(ww), 0), NDIM - 1);
    out[IMG_ELEMS + lin] = (float)__ldg(&lab[VIDX(nd, nh, nw)]);
    #undef VIDX
}

// ---------------------------------------------------------------------------
// kernel_launch — graph-capturable, allocation-free
// ---------------------------------------------------------------------------
extern "C" void kernel_launch(void* const* d_in, const int* in_sizes, int n_in,
                              void* d_out, int out_size) {
    const float4* img    = (const float4*)d_in[0];  // image_volume [2,128,128,128,4] f32
    const int*    lab    = (const int*)d_in[1];     // label_volume [2,128,128,128,1] i32
    const float*  coarse = (const float*)d_in[2];   // coarse_flow  [2,4,4,4,3] f32
    float*        out    = (float*)d_out;

    build_M_kernel<<<1, NDIM>>>();
    build_T2_kernel<<<dim3(NDIM, NB), NDIM>>>(coarse);
    warp_kernel<<<dim3(NDIM, NDIM, NB), NDIM>>>(img, lab, out);
}